// round 5
// baseline (speedup 1.0000x reference)
#include <cuda_runtime.h>

#define BATCH   16384
#define SEQ_L   64
#define T_STEPS 32
#define NH      128

typedef unsigned long long u64;

// ---------------- packed fp32x2 helpers (sm_100+) ----------------
__device__ __forceinline__ u64 pack2(float x, float y) {
    u64 r; asm("mov.b64 %0,{%1,%2};" : "=l"(r) : "f"(x), "f"(y)); return r;
}
__device__ __forceinline__ void unpack2(u64 v, float& x, float& y) {
    asm("mov.b64 {%0,%1},%2;" : "=f"(x), "=f"(y) : "l"(v));
}
__device__ __forceinline__ u64 fma2(u64 a, u64 b, u64 c) {
    u64 d; asm("fma.rn.f32x2 %0,%1,%2,%3;" : "=l"(d) : "l"(a), "l"(b), "l"(c)); return d;
}
__device__ __forceinline__ u64 dup2(float x) { return pack2(x, x); }

__device__ __forceinline__ float sigf(float x) {
    return __fdividef(1.0f, 1.0f + __expf(-x));
}
__device__ __forceinline__ float tanhfast(float x) {
    return 1.0f - 2.0f * __fdividef(1.0f, __expf(2.0f * x) + 1.0f);
}

// hidden-state scratch: [B][T][NH] fp32 = 256 MB
__device__ float g_hs[(size_t)BATCH * T_STEPS * NH];

// ---- GRU kernel smem layout (bytes) ----
// sW   : W_hh k-major fp32 [k=128][gj=384]            196608
// sHTd : h transposed, dup-packed u64 [k=128][row 272B: 16 samples * 8B + pad]
//        row stride 272B -> 4-way-conflict stores, aligned LDS.128 reads  34816
// sD   : teacher-forced 2-bit patch   [t=32][s=16]    512
#define G_OFFW 0
#define G_OFFH 196608
#define G_HROW 272
#define G_OFFD (G_OFFH + 128 * G_HROW)     // 231424
#define G_SMEM (G_OFFD + 512)              // 231936 (< 232448 max dyn)

__global__ __launch_bounds__(256, 1) void gru_kernel(
    const float* __restrict__ x, const float* __restrict__ w_ih,
    const float* __restrict__ w_hh, const float* __restrict__ b_ih,
    const float* __restrict__ b_hh)
{
    extern __shared__ char sm[];
    float* sW = (float*)(sm + G_OFFW);
    unsigned char* sD = (unsigned char*)(sm + G_OFFD);

    const int tid = threadIdx.x;
    const int c = tid & 63;          // j-pair index (j0 = 2c)
    const int grp = tid >> 6;        // sample group: samples grp*4 .. grp*4+3
    const int bBase = blockIdx.x * 16;
    const int j0 = 2 * c;

    // Stage W_hh transposed to k-major
    for (int i = tid; i < 384 * 128; i += 256) {
        int gj = i >> 7, k = i & 127;
        sW[k * 384 + gj] = w_hh[i];
    }
    // Teacher-forced input bits: data[t] = patches[t-1] (zeros at t=0)
    for (int i = tid; i < 32 * 16; i += 256) {
        int t = i >> 4, s = i & 15;
        unsigned char bits = 0;
        if (t > 0) {
            const float* xb = x + (size_t)(bBase + s) * SEQ_L + 2 * (t - 1);
            bits = (unsigned char)((xb[0] != 0.0f ? 1 : 0) | (xb[1] != 0.0f ? 2 : 0));
        }
        sD[i] = bits;
    }
    // zero h tile (h0 = 0)
    for (int i = tid; i < (128 * G_HROW) / 8; i += 256)
        ((u64*)(sm + G_OFFH))[i] = 0ULL;

    // Per-thread input-side params for its j-pair (gates r,z,n)
    u64 wiR0 = pack2(w_ih[(0 * 128 + j0) * 2 + 0], w_ih[(0 * 128 + j0 + 1) * 2 + 0]);
    u64 wiR1 = pack2(w_ih[(0 * 128 + j0) * 2 + 1], w_ih[(0 * 128 + j0 + 1) * 2 + 1]);
    u64 wiZ0 = pack2(w_ih[(1 * 128 + j0) * 2 + 0], w_ih[(1 * 128 + j0 + 1) * 2 + 0]);
    u64 wiZ1 = pack2(w_ih[(1 * 128 + j0) * 2 + 1], w_ih[(1 * 128 + j0 + 1) * 2 + 1]);
    u64 wiN0 = pack2(w_ih[(2 * 128 + j0) * 2 + 0], w_ih[(2 * 128 + j0 + 1) * 2 + 0]);
    u64 wiN1 = pack2(w_ih[(2 * 128 + j0) * 2 + 1], w_ih[(2 * 128 + j0 + 1) * 2 + 1]);
    u64 baseR = pack2(b_ih[j0] + b_hh[j0], b_ih[j0 + 1] + b_hh[j0 + 1]);
    u64 baseZ = pack2(b_ih[128 + j0] + b_hh[128 + j0], b_ih[128 + j0 + 1] + b_hh[128 + j0 + 1]);
    u64 binN  = pack2(b_ih[256 + j0], b_ih[256 + j0 + 1]);
    u64 bhnN  = pack2(b_hh[256 + j0], b_hh[256 + j0 + 1]);

    u64 hprev[4];
    #pragma unroll
    for (int s = 0; s < 4; s++) hprev[s] = 0ULL;

    __syncthreads();

    for (int t = 0; t < T_STEPS; t++) {
        u64 aR[4], aZ[4], aN[4], gN[4];
        #pragma unroll
        for (int s = 0; s < 4; s++) {
            unsigned char bits = sD[t * 16 + grp * 4 + s];
            u64 d0 = dup2((bits & 1) ? 1.0f : 0.0f);
            u64 d1 = dup2((bits & 2) ? 1.0f : 0.0f);
            aR[s] = fma2(d0, wiR0, fma2(d1, wiR1, baseR));
            aZ[s] = fma2(d0, wiZ0, fma2(d1, wiZ1, baseZ));
            gN[s] = fma2(d0, wiN0, fma2(d1, wiN1, binN));
            aN[s] = bhnN;   // b_hh_n seeds recurrent part (lives inside r*(...))
        }

        const char* hbase = sm + G_OFFH + grp * 32;
        #pragma unroll 8
        for (int k = 0; k < 128; k++) {
            const u64* wk = (const u64*)(sW + k * 384);
            u64 wr = wk[c];
            u64 wz = wk[64 + c];
            u64 wn = wk[128 + c];
            const ulonglong2* hk = (const ulonglong2*)(hbase + k * G_HROW);
            ulonglong2 ha = hk[0];          // samples grp*4+0, grp*4+1 (dup-packed)
            ulonglong2 hb = hk[1];          // samples grp*4+2, grp*4+3
            aR[0] = fma2(ha.x, wr, aR[0]);  aR[1] = fma2(ha.y, wr, aR[1]);
            aR[2] = fma2(hb.x, wr, aR[2]);  aR[3] = fma2(hb.y, wr, aR[3]);
            aZ[0] = fma2(ha.x, wz, aZ[0]);  aZ[1] = fma2(ha.y, wz, aZ[1]);
            aZ[2] = fma2(hb.x, wz, aZ[2]);  aZ[3] = fma2(hb.y, wz, aZ[3]);
            aN[0] = fma2(ha.x, wn, aN[0]);  aN[1] = fma2(ha.y, wn, aN[1]);
            aN[2] = fma2(hb.x, wn, aN[2]);  aN[3] = fma2(hb.y, wn, aN[3]);
        }

        __syncthreads();   // all reads of the h tile done

        #pragma unroll
        for (int s = 0; s < 4; s++) {
            float rx, ry, zx, zy, nx, ny, gx, gy, hx, hy;
            unpack2(aR[s], rx, ry);
            unpack2(aZ[s], zx, zy);
            unpack2(aN[s], nx, ny);
            unpack2(gN[s], gx, gy);
            unpack2(hprev[s], hx, hy);
            rx = sigf(rx); ry = sigf(ry);
            zx = sigf(zx); zy = sigf(zy);
            nx = tanhfast(gx + rx * nx);
            ny = tanhfast(gy + ry * ny);
            hx = (1.0f - zx) * nx + zx * hx;
            hy = (1.0f - zy) * ny + zy * hy;
            hprev[s] = pack2(hx, hy);
            int sg = grp * 4 + s;
            // dup-packed transposed store: sHTd[j][sg] = (h,h)
            *(u64*)(sm + G_OFFH + j0 * G_HROW + sg * 8)       = dup2(hx);
            *(u64*)(sm + G_OFFH + (j0 + 1) * G_HROW + sg * 8) = dup2(hy);
            *(float2*)(g_hs + ((size_t)(bBase + sg) * T_STEPS + t) * NH + j0)
                = make_float2(hx, hy);
        }
        __syncthreads();
    }
}

// ---- head kernel smem layout ----
#define H_OFFW1 0                              // w1 k-major fp32 [128][128] 65536
#define H_OFFH  65536                          // h dup tile [128][272B]     34816
#define H_HROW  272
#define H_OFFHID (H_OFFH + 128 * H_HROW)       // 100352: hid [16][130] f32  8320
#define H_OFFW2  (H_OFFHID + 16 * 130 * 4)     // 108672: w2 [4][132] f32    2112
#define H_OFFLOG (H_OFFW2 + 4 * 132 * 4)       // 110784: logits [64] f32    256
#define H_SMEM   (H_OFFLOG + 256)              // 111040 -> 2 CTAs/SM

__global__ __launch_bounds__(256, 2) void head_kernel(
    const float* __restrict__ x, const float* __restrict__ w1,
    const float* __restrict__ b1, const float* __restrict__ w2,
    const float* __restrict__ b2, float* __restrict__ out)
{
    extern __shared__ char sm[];
    float* sW1  = (float*)(sm + H_OFFW1);
    float* sHid = (float*)(sm + H_OFFHID);
    float* sW2  = (float*)(sm + H_OFFW2);
    float* sLog = (float*)(sm + H_OFFLOG);

    const int tid = threadIdx.x;
    const int c = tid & 63, grp = tid >> 6;
    const int bBase = blockIdx.x * 16;
    const int j0 = 2 * c;

    for (int i = tid; i < 128 * 128; i += 256) {
        int j = i >> 7, k = i & 127;
        sW1[k * 128 + j] = w1[i];
    }
    for (int i = tid; i < 4 * 128; i += 256) {
        int o = i >> 7, k = i & 127;
        sW2[o * 132 + k] = w2[i];
    }
    u64 bias1 = pack2(b1[j0], b1[j0 + 1]);
    float acc = 0.0f;
    __syncthreads();

    for (int t = 0; t < T_STEPS; t++) {
        // stage h_t, dup-packed transposed (coalesced global read)
        for (int i = tid; i < 16 * 128; i += 256) {
            int s = i >> 7, k = i & 127;
            float h = g_hs[((size_t)(bBase + s) * T_STEPS + t) * NH + k];
            *(u64*)(sm + H_OFFH + k * H_HROW + s * 8) = dup2(h);
        }
        __syncthreads();

        // hid = relu(h @ w1^T + b1)
        u64 a[4];
        #pragma unroll
        for (int s = 0; s < 4; s++) a[s] = bias1;
        const char* hbase = sm + H_OFFH + grp * 32;
        #pragma unroll 8
        for (int k = 0; k < 128; k++) {
            u64 w = ((const u64*)(sW1 + k * 128))[c];
            const ulonglong2* hk = (const ulonglong2*)(hbase + k * H_HROW);
            ulonglong2 ha = hk[0];
            ulonglong2 hb = hk[1];
            a[0] = fma2(ha.x, w, a[0]);
            a[1] = fma2(ha.y, w, a[1]);
            a[2] = fma2(hb.x, w, a[2]);
            a[3] = fma2(hb.y, w, a[3]);
        }
        #pragma unroll
        for (int s = 0; s < 4; s++) {
            float hx, hy;
            unpack2(a[s], hx, hy);
            hx = fmaxf(hx, 0.0f);
            hy = fmaxf(hy, 0.0f);
            *(float2*)(sHid + (grp * 4 + s) * 130 + j0) = make_float2(hx, hy);
        }
        __syncthreads();

        // logits: 16 samples x 4 classes on the first 64 threads
        if (tid < 64) {
            int s = tid >> 2, o = tid & 3;
            float d = b2[o];
            #pragma unroll 8
            for (int k = 0; k < 128; k++)
                d += sHid[s * 130 + k] * sW2[o * 132 + k];
            sLog[tid] = d;
        }
        __syncthreads();

        // per-sample log-prob of the true patch
        if (tid < 16) {
            size_t b = (size_t)(bBase + tid) * SEQ_L;
            int i0 = (x[b + 2 * t] != 0.0f) ? 1 : 0;
            int i1 = (x[b + 2 * t + 1] != 0.0f) ? 1 : 0;
            int idx = i0 + 2 * i1;
            float l0 = sLog[tid * 4], l1 = sLog[tid * 4 + 1];
            float l2 = sLog[tid * 4 + 2], l3 = sLog[tid * 4 + 3];
            float m = fmaxf(fmaxf(l0, l1), fmaxf(l2, l3));
            float lse = m + __logf(__expf(l0 - m) + __expf(l1 - m) +
                                   __expf(l2 - m) + __expf(l3 - m));
            acc += sLog[tid * 4 + idx] - lse;
        }
        __syncthreads();
    }
    if (tid < 16) out[bBase + tid] = acc;
}

extern "C" void kernel_launch(void* const* d_in, const int* in_sizes, int n_in,
                              void* d_out, int out_size) {
    const float* x    = (const float*)d_in[0];
    const float* w_ih = (const float*)d_in[1];
    const float* w_hh = (const float*)d_in[2];
    const float* b_ih = (const float*)d_in[3];
    const float* b_hh = (const float*)d_in[4];
    const float* w1   = (const float*)d_in[5];
    const float* b1   = (const float*)d_in[6];
    const float* w2   = (const float*)d_in[7];
    const float* b2   = (const float*)d_in[8];
    float* out = (float*)d_out;

    cudaFuncSetAttribute(gru_kernel, cudaFuncAttributeMaxDynamicSharedMemorySize, G_SMEM);
    cudaFuncSetAttribute(head_kernel, cudaFuncAttributeMaxDynamicSharedMemorySize, H_SMEM);

    gru_kernel<<<BATCH / 16, 256, G_SMEM>>>(x, w_ih, w_hh, b_ih, b_hh);
    head_kernel<<<BATCH / 16, 256, H_SMEM>>>(x, w1, b1, w2, b2, out);
}

// round 6
// speedup vs baseline: 1.7510x; 1.7510x over previous
#include <cuda_runtime.h>
#include <cstdint>

#define BATCH   16384
#define SEQ_L   64
#define T_STEPS 32
#define NH      128

typedef unsigned long long u64;

// ---------------- fp32x2 helpers (head kernel) ----------------
__device__ __forceinline__ u64 pack2(float x, float y) {
    u64 r; asm("mov.b64 %0,{%1,%2};" : "=l"(r) : "f"(x), "f"(y)); return r;
}
__device__ __forceinline__ void unpack2(u64 v, float& x, float& y) {
    asm("mov.b64 {%0,%1},%2;" : "=f"(x), "=f"(y) : "l"(v));
}
__device__ __forceinline__ u64 fma2(u64 a, u64 b, u64 c) {
    u64 d; asm("fma.rn.f32x2 %0,%1,%2,%3;" : "=l"(d) : "l"(a), "l"(b), "l"(c)); return d;
}
__device__ __forceinline__ u64 dup2(float x) { return pack2(x, x); }

__device__ __forceinline__ float sigf(float x) {
    return __fdividef(1.0f, 1.0f + __expf(-x));
}
__device__ __forceinline__ float tanhfast(float x) {
    return 1.0f - 2.0f * __fdividef(1.0f, __expf(2.0f * x) + 1.0f);
}

// ---------------- device scratch ----------------
__device__ float    g_hs[(size_t)BATCH * T_STEPS * NH];   // [B][T][NH]
__device__ uint32_t g_whhF[16 * 48 * 32 * 2];             // W_hh tf32 frags
__device__ uint32_t g_w1F [16 * 16 * 32 * 2];             // w1  tf32 frags

__device__ __forceinline__ uint32_t f2tf32(float v) {
    uint32_t t; asm("cvt.rna.tf32.f32 %0, %1;" : "=r"(t) : "f"(v)); return t;
}

// ---------------- mma.sync m16n8k8 tf32 ----------------
__device__ __forceinline__ void mma8(float* d, const uint32_t* a, uint32_t b0, uint32_t b1) {
    asm("mma.sync.aligned.m16n8k8.row.col.f32.tf32.tf32.f32 "
        "{%0,%1,%2,%3}, {%4,%5,%6,%7}, {%8,%9}, {%0,%1,%2,%3};"
        : "+f"(d[0]), "+f"(d[1]), "+f"(d[2]), "+f"(d[3])
        : "r"(a[0]), "r"(a[1]), "r"(a[2]), "r"(a[3]), "r"(b0), "r"(b1));
}

// ============================================================================
// Pre-kernel: build tf32 B-fragments for W_hh [384][128] and w1 [128][128].
// frag(kc,nf,lane,b): element B[k][n] with n = nf*8 + (lane>>2),
//                     k = kc*8 + (lane&3) + b*4, B[k][n] = W[n][k].
// ============================================================================
__global__ void conv_kernel(const float* __restrict__ w_hh, const float* __restrict__ w1) {
    int i = blockIdx.x * 256 + threadIdx.x;   // 0..65535
    if (i < 16 * 48 * 32 * 2) {
        int b = i & 1, lane = (i >> 1) & 31, nf = (i >> 6) % 48, kc = (i >> 6) / 48;
        int n = nf * 8 + (lane >> 2);
        int k = kc * 8 + (lane & 3) + b * 4;
        g_whhF[i] = f2tf32(w_hh[n * 128 + k]);
    } else {
        int i2 = i - 16 * 48 * 32 * 2;
        int b = i2 & 1, lane = (i2 >> 1) & 31, nf = (i2 >> 6) % 16, kc = (i2 >> 6) / 16;
        int n = nf * 8 + (lane >> 2);
        int k = kc * 8 + (lane & 3) + b * 4;
        g_w1F[i2] = f2tf32(w1[n * 128 + k]);
    }
}

// ============================================================================
// GRU kernel (tensor cores). 64 samples/CTA, 256 threads = 8 warps.
// Warp w owns j-slice [w*16, w*16+16) for ALL 64 rows and all 3 gates.
// A (=h, tf32 bits) in smem [64][132]; B frags from L2-resident globals.
// ============================================================================
#define GS_A   0                      // uint32 sA[64*132]            33792 B
#define GS_XI  33792                  // float4 xi[4 variants][128 j]  8192 B
#define GS_D   41984                  // uint8  sD[32][64]             2048 B
#define GS_SZ  44032

__global__ __launch_bounds__(256, 1) void gru_mma_kernel(
    const float* __restrict__ x, const float* __restrict__ w_ih,
    const float* __restrict__ b_ih, const float* __restrict__ b_hh)
{
    extern __shared__ char smc[];
    uint32_t* sA = (uint32_t*)(smc + GS_A);
    float4*   sXI = (float4*)(smc + GS_XI);
    unsigned char* sD = (unsigned char*)(smc + GS_D);

    const int tid  = threadIdx.x;
    const int wid  = tid >> 5, lane = tid & 31;
    const int rg   = lane >> 2, c4 = lane & 3;
    const int j0   = wid * 16;
    const int bBase = blockIdx.x * 64;

    // ---- staging ----
    // xi table: [v][j] = {xi_r, xi_z, xi_n, b_hh_n}; xi_g = b_ih_g (+b_hh_g for r,z) + bits·w_ih_g
    for (int i = tid; i < 4 * 128; i += 256) {
        int v = i >> 7, j = i & 127;
        float xr = b_ih[j] + b_hh[j];
        float xz = b_ih[128 + j] + b_hh[128 + j];
        float xn = b_ih[256 + j];
        if (v & 1) { xr += w_ih[j * 2]; xz += w_ih[(128 + j) * 2]; xn += w_ih[(256 + j) * 2]; }
        if (v & 2) { xr += w_ih[j * 2 + 1]; xz += w_ih[(128 + j) * 2 + 1]; xn += w_ih[(256 + j) * 2 + 1]; }
        sXI[i] = make_float4(xr, xz, xn, b_hh[256 + j]);
    }
    // teacher-forced 2-bit inputs: v(t,s) = patch(t-1), 0 at t=0
    for (int i = tid; i < 32 * 64; i += 256) {
        int t = i >> 6, s = i & 63;
        unsigned char bits = 0;
        if (t > 0) {
            const float* xb = x + (size_t)(bBase + s) * SEQ_L + 2 * (t - 1);
            bits = (unsigned char)((xb[0] != 0.0f ? 1 : 0) | (xb[1] != 0.0f ? 2 : 0));
        }
        sD[i] = bits;
    }
    for (int i = tid; i < 64 * 132; i += 256) sA[i] = 0u;   // h0 = 0 (tf32 bits of 0)

    float hp[4][2][4];      // fp32 h_prev for owned (row,col) elements
    #pragma unroll
    for (int m = 0; m < 4; m++)
        #pragma unroll
        for (int f = 0; f < 2; f++)
            #pragma unroll
            for (int e = 0; e < 4; e++) hp[m][f][e] = 0.0f;

    __syncthreads();

    const uint2* gW = (const uint2*)g_whhF;

    for (int t = 0; t < T_STEPS; t++) {
        // ---- recurrent GEMM: gh = h @ W_hh^T for this warp's j-slice, 3 gates ----
        float aR[4][2][4], aZ[4][2][4], aN[4][2][4];
        #pragma unroll
        for (int m = 0; m < 4; m++)
            #pragma unroll
            for (int f = 0; f < 2; f++)
                #pragma unroll
                for (int e = 0; e < 4; e++) { aR[m][f][e] = 0.f; aZ[m][f][e] = 0.f; aN[m][f][e] = 0.f; }

        #pragma unroll
        for (int kc = 0; kc < 16; kc++) {
            uint32_t A[4][4];
            #pragma unroll
            for (int m = 0; m < 4; m++) {
                int base = (m * 16 + rg) * 132 + kc * 8 + c4;
                A[m][0] = sA[base];
                A[m][1] = sA[base + 8 * 132];
                A[m][2] = sA[base + 4];
                A[m][3] = sA[base + 8 * 132 + 4];
            }
            #pragma unroll
            for (int f = 0; f < 2; f++) {
                uint2 Br = gW[(kc * 48 + 0 * 16 + wid * 2 + f) * 32 + lane];
                uint2 Bz = gW[(kc * 48 + 1 * 16 + wid * 2 + f) * 32 + lane];
                uint2 Bn = gW[(kc * 48 + 2 * 16 + wid * 2 + f) * 32 + lane];
                #pragma unroll
                for (int m = 0; m < 4; m++) {
                    mma8(aR[m][f], A[m], Br.x, Br.y);
                    mma8(aZ[m][f], A[m], Bz.x, Bz.y);
                    mma8(aN[m][f], A[m], Bn.x, Bn.y);
                }
            }
        }

        __syncthreads();   // all A reads done before epilogue rewrites sA

        // ---- epilogue: gates -> h; write sA (tf32) + g_hs (fp32) ----
        #pragma unroll
        for (int m = 0; m < 4; m++) {
            #pragma unroll
            for (int rr = 0; rr < 2; rr++) {
                int row = m * 16 + rg + rr * 8;
                int v = sD[t * 64 + row];
                #pragma unroll
                for (int f = 0; f < 2; f++) {
                    int col0 = j0 + f * 8 + 2 * c4;
                    int e0 = rr * 2;           // (row, col0)
                    int e1 = rr * 2 + 1;       // (row, col0+1)
                    float4 xiA = sXI[v * 128 + col0];
                    float4 xiB = sXI[v * 128 + col0 + 1];
                    float r0 = sigf(aR[m][f][e0] + xiA.x);
                    float r1 = sigf(aR[m][f][e1] + xiB.x);
                    float z0 = sigf(aZ[m][f][e0] + xiA.y);
                    float z1 = sigf(aZ[m][f][e1] + xiB.y);
                    float n0 = tanhfast(xiA.z + r0 * (aN[m][f][e0] + xiA.w));
                    float n1 = tanhfast(xiB.z + r1 * (aN[m][f][e1] + xiB.w));
                    float h0 = n0 + z0 * (hp[m][f][e0] - n0);
                    float h1 = n1 + z1 * (hp[m][f][e1] - n1);
                    hp[m][f][e0] = h0; hp[m][f][e1] = h1;
                    // sA: tf32 bits, adjacent cols -> one 8B store
                    uint2 hb = make_uint2(f2tf32(h0), f2tf32(h1));
                    *(uint2*)&sA[row * 132 + col0] = hb;
                    // g_hs: fp32 for the head kernel
                    *(float2*)(g_hs + ((size_t)(bBase + row) * T_STEPS + t) * NH + col0)
                        = make_float2(h0, h1);
                }
            }
        }
        __syncthreads();   // sA fully written before next step's GEMM
    }
}

// ============================================================================
// Head kernel (unchanged from the passing R4 version)
// ============================================================================
#define H_OFFW1 0
#define H_OFFH  65536
#define H_HROW  272
#define H_OFFHID (H_OFFH + 128 * H_HROW)
#define H_OFFW2  (H_OFFHID + 16 * 130 * 4)
#define H_OFFLOG (H_OFFW2 + 4 * 132 * 4)
#define H_SMEM   (H_OFFLOG + 256)

__global__ __launch_bounds__(256, 2) void head_kernel(
    const float* __restrict__ x, const float* __restrict__ w1,
    const float* __restrict__ b1, const float* __restrict__ w2,
    const float* __restrict__ b2, float* __restrict__ out)
{
    extern __shared__ char sm[];
    float* sW1  = (float*)(sm + H_OFFW1);
    float* sHid = (float*)(sm + H_OFFHID);
    float* sW2  = (float*)(sm + H_OFFW2);
    float* sLog = (float*)(sm + H_OFFLOG);

    const int tid = threadIdx.x;
    const int c = tid & 63, grp = tid >> 6;
    const int bBase = blockIdx.x * 16;
    const int j0 = 2 * c;

    for (int i = tid; i < 128 * 128; i += 256) {
        int j = i >> 7, k = i & 127;
        sW1[k * 128 + j] = w1[i];
    }
    for (int i = tid; i < 4 * 128; i += 256) {
        int o = i >> 7, k = i & 127;
        sW2[o * 132 + k] = w2[i];
    }
    u64 bias1 = pack2(b1[j0], b1[j0 + 1]);
    float acc = 0.0f;
    __syncthreads();

    for (int t = 0; t < T_STEPS; t++) {
        for (int i = tid; i < 16 * 128; i += 256) {
            int s = i >> 7, k = i & 127;
            float h = g_hs[((size_t)(bBase + s) * T_STEPS + t) * NH + k];
            *(u64*)(sm + H_OFFH + k * H_HROW + s * 8) = dup2(h);
        }
        __syncthreads();

        u64 a[4];
        #pragma unroll
        for (int s = 0; s < 4; s++) a[s] = bias1;
        const char* hbase = sm + H_OFFH + grp * 32;
        #pragma unroll 8
        for (int k = 0; k < 128; k++) {
            u64 w = ((const u64*)(sW1 + k * 128))[c];
            const ulonglong2* hk = (const ulonglong2*)(hbase + k * H_HROW);
            ulonglong2 ha = hk[0];
            ulonglong2 hb = hk[1];
            a[0] = fma2(ha.x, w, a[0]);
            a[1] = fma2(ha.y, w, a[1]);
            a[2] = fma2(hb.x, w, a[2]);
            a[3] = fma2(hb.y, w, a[3]);
        }
        #pragma unroll
        for (int s = 0; s < 4; s++) {
            float hx, hy;
            unpack2(a[s], hx, hy);
            hx = fmaxf(hx, 0.0f);
            hy = fmaxf(hy, 0.0f);
            *(float2*)(sHid + (grp * 4 + s) * 130 + j0) = make_float2(hx, hy);
        }
        __syncthreads();

        if (tid < 64) {
            int s = tid >> 2, o = tid & 3;
            float d = b2[o];
            #pragma unroll 8
            for (int k = 0; k < 128; k++)
                d += sHid[s * 130 + k] * sW2[o * 132 + k];
            sLog[tid] = d;
        }
        __syncthreads();

        if (tid < 16) {
            size_t b = (size_t)(bBase + tid) * SEQ_L;
            int i0 = (x[b + 2 * t] != 0.0f) ? 1 : 0;
            int i1 = (x[b + 2 * t + 1] != 0.0f) ? 1 : 0;
            int idx = i0 + 2 * i1;
            float l0 = sLog[tid * 4], l1 = sLog[tid * 4 + 1];
            float l2 = sLog[tid * 4 + 2], l3 = sLog[tid * 4 + 3];
            float m = fmaxf(fmaxf(l0, l1), fmaxf(l2, l3));
            float lse = m + __logf(__expf(l0 - m) + __expf(l1 - m) +
                                   __expf(l2 - m) + __expf(l3 - m));
            acc += sLog[tid * 4 + idx] - lse;
        }
        __syncthreads();
    }
    if (tid < 16) out[bBase + tid] = acc;
}

extern "C" void kernel_launch(void* const* d_in, const int* in_sizes, int n_in,
                              void* d_out, int out_size) {
    const float* x    = (const float*)d_in[0];
    const float* w_ih = (const float*)d_in[1];
    const float* w_hh = (const float*)d_in[2];
    const float* b_ih = (const float*)d_in[3];
    const float* b_hh = (const float*)d_in[4];
    const float* w1   = (const float*)d_in[5];
    const float* b1   = (const float*)d_in[6];
    const float* w2   = (const float*)d_in[7];
    const float* b2   = (const float*)d_in[8];
    float* out = (float*)d_out;

    cudaFuncSetAttribute(gru_mma_kernel, cudaFuncAttributeMaxDynamicSharedMemorySize, GS_SZ);
    cudaFuncSetAttribute(head_kernel, cudaFuncAttributeMaxDynamicSharedMemorySize, H_SMEM);

    conv_kernel<<<256, 256>>>(w_hh, w1);
    gru_mma_kernel<<<BATCH / 64, 256, GS_SZ>>>(x, w_ih, b_ih, b_hh);
    head_kernel<<<BATCH / 16, 256, H_SMEM>>>(x, w1, b1, w2, b2, out);
}

// round 7
// speedup vs baseline: 6.9046x; 3.9433x over previous
#include <cuda_runtime.h>
#include <cstdint>

#define BATCH   16384
#define SEQ_L   64
#define T_STEPS 32
#define NH      128
#define TPC     64
#define NCTA    (BATCH / TPC)   // 256
#define THREADS 256

typedef unsigned long long u64;

// ---------------- smem layout (bytes) ----------------
#define S_BW   0                 // W_hh bf16 B-frags: 8kc*48nf*32lane uint2 = 98304
#define S_BW1  98304             // w1  bf16 B-frags: 8kc*16nf*32lane uint2 = 32768
#define S_A    131072            // h tile bf16 [64 rows][136 cols]          = 17408
#define S_HID  148480            // hid f32 [64][132]                        = 33792
#define S_XI   182272            // float4 xi [4 variants][128 j]            = 8192
#define S_P    190464            // uint8 patch idx [32][64]                 = 2048
#define S_LOG  192512            // f32 logits [64][4]                       = 1024
#define S_W2   193536            // f32 w2 [4][132]                          = 2112
#define S_B1   195648            // f32 b1 [128]                             = 512
#define SMEM_TOTAL 196160

// ---------------- helpers ----------------
__device__ __forceinline__ uint32_t s2u(const void* p) {
    uint32_t a;
    asm("{ .reg .u64 t; cvta.to.shared.u64 t, %1; cvt.u32.u64 %0, t; }" : "=r"(a) : "l"(p));
    return a;
}
__device__ __forceinline__ uint32_t bf2(float lo, float hi) {
    uint32_t r; asm("cvt.rn.bf16x2.f32 %0, %1, %2;" : "=r"(r) : "f"(hi), "f"(lo)); return r;
}
__device__ __forceinline__ void ldm4(uint32_t* a, uint32_t addr) {
    asm volatile("ldmatrix.sync.aligned.m8n8.x4.shared.b16 {%0,%1,%2,%3}, [%4];"
        : "=r"(a[0]), "=r"(a[1]), "=r"(a[2]), "=r"(a[3]) : "r"(addr));
}
__device__ __forceinline__ void mma16(float* d, const uint32_t* a, uint2 b) {
    asm volatile("mma.sync.aligned.m16n8k16.row.col.f32.bf16.bf16.f32 "
        "{%0,%1,%2,%3},{%4,%5,%6,%7},{%8,%9},{%0,%1,%2,%3};"
        : "+f"(d[0]), "+f"(d[1]), "+f"(d[2]), "+f"(d[3])
        : "r"(a[0]), "r"(a[1]), "r"(a[2]), "r"(a[3]), "r"(b.x), "r"(b.y));
}
__device__ __forceinline__ float tanha(float x) {
    float y; asm("tanh.approx.f32 %0,%1;" : "=f"(y) : "f"(x)); return y;
}
__device__ __forceinline__ float siga(float x) {      // sigmoid via tanh.approx
    return fmaf(0.5f, tanha(0.5f * x), 0.5f);
}
// f32x2 (for the logits dot)
__device__ __forceinline__ u64 fma2(u64 a, u64 b, u64 c) {
    u64 d; asm("fma.rn.f32x2 %0,%1,%2,%3;" : "=l"(d) : "l"(a), "l"(b), "l"(c)); return d;
}
__device__ __forceinline__ void unpack2(u64 v, float& x, float& y) {
    asm("mov.b64 {%0,%1},%2;" : "=f"(x), "=f"(y) : "l"(v));
}

// ============================================================================
// Fully fused PRNN kernel. 64 samples/CTA, 256 threads (8 warps).
// Warp w owns j-slice [16w, 16w+16) of all 64 rows, all 3 gates + hid.
// sA holds h_{t-1} (bf16). Iter t: [hid mma for step t-1] + [gate mma for
// step t] on the same A tile; epilogues update sA / sHid; logits+lse SIMT.
// ============================================================================
__global__ __launch_bounds__(THREADS, 1) void prnn_kernel(
    const float* __restrict__ x, const float* __restrict__ w_ih,
    const float* __restrict__ w_hh, const float* __restrict__ b_ih,
    const float* __restrict__ b_hh, const float* __restrict__ w1,
    const float* __restrict__ b1, const float* __restrict__ w2,
    const float* __restrict__ b2, float* __restrict__ out)
{
    extern __shared__ char sm[];
    uint2*  sBW  = (uint2*)(sm + S_BW);
    uint2*  sBW1 = (uint2*)(sm + S_BW1);
    float*  sHid = (float*)(sm + S_HID);
    float4* sXI  = (float4*)(sm + S_XI);
    unsigned char* sP = (unsigned char*)(sm + S_P);
    float*  sLog = (float*)(sm + S_LOG);
    float*  sW2  = (float*)(sm + S_W2);
    float*  sB1  = (float*)(sm + S_B1);

    const int tid = threadIdx.x;
    const int wid = tid >> 5, lane = tid & 31;
    const int rg = lane >> 2, c4 = lane & 3;
    const int j0 = wid * 16;
    const int bBase = blockIdx.x * TPC;
    const uint32_t saB = s2u(sm + S_A);

    // ---- stage W_hh B-frags (bf16): frag(kc,nf,lane) covers B[k][n]=W_hh[n][k]
    //      n = nf*8 + (lane>>2), k0 = kc*16 + (lane&3)*2; b0 = k0,k0+1; b1 = +8
    for (int i = tid; i < 8 * 48 * 32; i += THREADS) {
        int ln = i & 31, nf = (i >> 5) % 48, kc = (i >> 5) / 48;
        const float* wr = w_hh + (nf * 8 + (ln >> 2)) * NH + kc * 16 + (ln & 3) * 2;
        sBW[i] = make_uint2(bf2(wr[0], wr[1]), bf2(wr[8], wr[9]));
    }
    // ---- stage w1 B-frags
    for (int i = tid; i < 8 * 16 * 32; i += THREADS) {
        int ln = i & 31, nf = (i >> 5) % 16, kc = (i >> 5) / 16;
        const float* wr = w1 + (nf * 8 + (ln >> 2)) * NH + kc * 16 + (ln & 3) * 2;
        sBW1[i] = make_uint2(bf2(wr[0], wr[1]), bf2(wr[8], wr[9]));
    }
    // ---- xi table: [v][j] = {xi_r, xi_z, xi_n, b_hh_n}
    for (int i = tid; i < 4 * NH; i += THREADS) {
        int v = i >> 7, j = i & 127;
        float xr = b_ih[j] + b_hh[j];
        float xz = b_ih[NH + j] + b_hh[NH + j];
        float xn = b_ih[2 * NH + j];
        if (v & 1) { xr += w_ih[j * 2]; xz += w_ih[(NH + j) * 2]; xn += w_ih[(2 * NH + j) * 2]; }
        if (v & 2) { xr += w_ih[j * 2 + 1]; xz += w_ih[(NH + j) * 2 + 1]; xn += w_ih[(2 * NH + j) * 2 + 1]; }
        sXI[i] = make_float4(xr, xz, xn, b_hh[2 * NH + j]);
    }
    for (int i = tid; i < 4 * NH; i += THREADS) {
        int o = i >> 7, k = i & 127;
        sW2[o * 132 + k] = w2[i];
    }
    for (int i = tid; i < NH; i += THREADS) sB1[i] = b1[i];
    // ---- patch indices per (t, row)
    for (int i = tid; i < T_STEPS * TPC; i += THREADS) {
        int t = i >> 6, s = i & 63;
        const float* xb = x + (size_t)(bBase + s) * SEQ_L + 2 * t;
        sP[i] = (unsigned char)((xb[0] != 0.0f ? 1 : 0) | (xb[1] != 0.0f ? 2 : 0));
    }
    // ---- zero A (h0 = 0); 64*136 bf16 = 4352 words
    for (int i = tid; i < 4352; i += THREADS) ((uint32_t*)(sm + S_A))[i] = 0u;

    float hp[4][2][4];
    #pragma unroll
    for (int m = 0; m < 4; m++)
        #pragma unroll
        for (int f = 0; f < 2; f++)
            #pragma unroll
            for (int e = 0; e < 4; e++) hp[m][f][e] = 0.0f;
    float acc = 0.0f;
    const float b2r = b2[tid & 3];

    // ldmatrix address: lanes 0-15 -> row=lane,k=0; 16-31 -> row=lane-16,k=8
    const uint32_t lmBase = saB + (uint32_t)(lane & 15) * 272 + (uint32_t)(lane >> 4) * 16;

    __syncthreads();

    for (int t = 0; t <= T_STEPS; t++) {
        // ---------- hid MMA for step t-1 (A = h_{t-1}) + its epilogue ----------
        if (t >= 1) {
            float aH[4][2][4];
            #pragma unroll
            for (int m = 0; m < 4; m++)
                #pragma unroll
                for (int f = 0; f < 2; f++)
                    #pragma unroll
                    for (int e = 0; e < 4; e++) aH[m][f][e] = 0.0f;
            #pragma unroll
            for (int kc = 0; kc < 8; kc++) {
                uint32_t A[4][4];
                #pragma unroll
                for (int m = 0; m < 4; m++) ldm4(A[m], lmBase + m * 16 * 272 + kc * 32);
                #pragma unroll
                for (int f = 0; f < 2; f++) {
                    uint2 B = sBW1[(kc * 16 + wid * 2 + f) * 32 + lane];
                    #pragma unroll
                    for (int m = 0; m < 4; m++) mma16(aH[m][f], A[m], B);
                }
            }
            // hid epilogue: relu(+b1) -> sHid
            #pragma unroll
            for (int m = 0; m < 4; m++)
                #pragma unroll
                for (int rr = 0; rr < 2; rr++) {
                    int row = m * 16 + rg + rr * 8;
                    #pragma unroll
                    for (int f = 0; f < 2; f++) {
                        int col0 = j0 + f * 8 + 2 * c4;
                        float h0 = fmaxf(aH[m][f][rr * 2]     + sB1[col0],     0.0f);
                        float h1 = fmaxf(aH[m][f][rr * 2 + 1] + sB1[col0 + 1], 0.0f);
                        *(float2*)(sHid + row * 132 + col0) = make_float2(h0, h1);
                    }
                }
        }

        // ---------- gate MMAs for step t (A = h_{t-1}) ----------
        float aR[4][2][4], aZ[4][2][4], aN[4][2][4];
        if (t < T_STEPS) {
            #pragma unroll
            for (int m = 0; m < 4; m++)
                #pragma unroll
                for (int f = 0; f < 2; f++)
                    #pragma unroll
                    for (int e = 0; e < 4; e++) { aR[m][f][e] = 0.f; aZ[m][f][e] = 0.f; aN[m][f][e] = 0.f; }
            #pragma unroll
            for (int kc = 0; kc < 8; kc++) {
                uint32_t A[4][4];
                #pragma unroll
                for (int m = 0; m < 4; m++) ldm4(A[m], lmBase + m * 16 * 272 + kc * 32);
                #pragma unroll
                for (int f = 0; f < 2; f++) {
                    uint2 Br = sBW[(kc * 48 + 0 * 16 + wid * 2 + f) * 32 + lane];
                    uint2 Bz = sBW[(kc * 48 + 1 * 16 + wid * 2 + f) * 32 + lane];
                    uint2 Bn = sBW[(kc * 48 + 2 * 16 + wid * 2 + f) * 32 + lane];
                    #pragma unroll
                    for (int m = 0; m < 4; m++) {
                        mma16(aR[m][f], A[m], Br);
                        mma16(aZ[m][f], A[m], Bz);
                        mma16(aN[m][f], A[m], Bn);
                    }
                }
            }
        }

        __syncthreads();   // all sA reads done

        // ---------- gate epilogue: h_t -> sA (bf16) ----------
        if (t < T_STEPS) {
            #pragma unroll
            for (int m = 0; m < 4; m++)
                #pragma unroll
                for (int rr = 0; rr < 2; rr++) {
                    int row = m * 16 + rg + rr * 8;
                    int v = (t > 0) ? sP[(t - 1) * TPC + row] : 0;
                    #pragma unroll
                    for (int f = 0; f < 2; f++) {
                        int col0 = j0 + f * 8 + 2 * c4;
                        int e0 = rr * 2, e1 = rr * 2 + 1;
                        float4 xa = sXI[v * NH + col0];
                        float4 xb = sXI[v * NH + col0 + 1];
                        float r0 = siga(aR[m][f][e0] + xa.x);
                        float r1 = siga(aR[m][f][e1] + xb.x);
                        float z0 = siga(aZ[m][f][e0] + xa.y);
                        float z1 = siga(aZ[m][f][e1] + xb.y);
                        float n0 = tanha(xa.z + r0 * (aN[m][f][e0] + xa.w));
                        float n1 = tanha(xb.z + r1 * (aN[m][f][e1] + xb.w));
                        float h0 = n0 + z0 * (hp[m][f][e0] - n0);
                        float h1 = n1 + z1 * (hp[m][f][e1] - n1);
                        hp[m][f][e0] = h0; hp[m][f][e1] = h1;
                        *(uint32_t*)(sm + S_A + row * 272 + col0 * 2) = bf2(h0, h1);
                    }
                }
        }

        __syncthreads();   // sA + sHid ready

        // ---------- logits for step t-1 ----------
        if (t >= 1) {
            int row = tid >> 2, o = tid & 3;
            u64 d2 = 0ULL;   // (0.0f, 0.0f)
            const u64* hv = (const u64*)(sHid + row * 132);
            const u64* wv = (const u64*)(sW2 + o * 132);
            #pragma unroll 16
            for (int k = 0; k < 64; k++) d2 = fma2(hv[k], wv[k], d2);
            float dx, dy; unpack2(d2, dx, dy);
            sLog[row * 4 + o] = dx + dy + b2r;
        }

        __syncthreads();   // sLog ready

        if (t >= 1 && tid < TPC) {
            float4 l = ((const float4*)sLog)[tid];
            float mx = fmaxf(fmaxf(l.x, l.y), fmaxf(l.z, l.w));
            float lse = mx + __logf(__expf(l.x - mx) + __expf(l.y - mx) +
                                    __expf(l.z - mx) + __expf(l.w - mx));
            int idx = sP[(t - 1) * TPC + tid];
            float pick = (idx == 0) ? l.x : (idx == 1) ? l.y : (idx == 2) ? l.z : l.w;
            acc += pick - lse;
        }
    }

    if (tid < TPC) out[bBase + tid] = acc;
}

extern "C" void kernel_launch(void* const* d_in, const int* in_sizes, int n_in,
                              void* d_out, int out_size) {
    const float* x    = (const float*)d_in[0];
    const float* w_ih = (const float*)d_in[1];
    const float* w_hh = (const float*)d_in[2];
    const float* b_ih = (const float*)d_in[3];
    const float* b_hh = (const float*)d_in[4];
    const float* w1   = (const float*)d_in[5];
    const float* b1   = (const float*)d_in[6];
    const float* w2   = (const float*)d_in[7];
    const float* b2   = (const float*)d_in[8];
    float* out = (float*)d_out;

    cudaFuncSetAttribute(prnn_kernel, cudaFuncAttributeMaxDynamicSharedMemorySize, SMEM_TOTAL);
    prnn_kernel<<<NCTA, THREADS, SMEM_TOTAL>>>(
        x, w_ih, w_hh, b_ih, b_hh, w1, b1, w2, b2, out);
}

// round 8
// speedup vs baseline: 7.2956x; 1.0566x over previous
#include <cuda_runtime.h>
#include <cstdint>

#define BATCH   16384
#define SEQ_L   64
#define T_STEPS 32
#define NH      128
#define TPC     64
#define NCTA    (BATCH / TPC)   // 256
#define THREADS 256

// ---------------- smem layout (bytes) ----------------
#define S_BW   0                 // W_hh bf16 B-frags: 8kc*48nf*32lane uint2 = 98304
#define S_BW1  98304             // w1  bf16 B-frags: 8kc*16nf*32lane uint2 = 32768
#define S_A    131072            // h tile bf16 [64 rows][136 cols]          = 17408
#define S_XI   148480            // float4 xi [4 variants][128 j]            = 8192
#define S_P    156672            // uint8 patch idx [32][64]                 = 2048
#define S_PART 158720            // f32 partial logits [2 par][8 w][64][4]   = 16384
#define SMEM_TOTAL 175104

// ---------------- helpers ----------------
__device__ __forceinline__ uint32_t s2u(const void* p) {
    uint32_t a;
    asm("{ .reg .u64 t; cvta.to.shared.u64 t, %1; cvt.u32.u64 %0, t; }" : "=r"(a) : "l"(p));
    return a;
}
__device__ __forceinline__ uint32_t bf2(float lo, float hi) {
    uint32_t r; asm("cvt.rn.bf16x2.f32 %0, %1, %2;" : "=r"(r) : "f"(hi), "f"(lo)); return r;
}
__device__ __forceinline__ void ldm4(uint32_t* a, uint32_t addr) {
    asm volatile("ldmatrix.sync.aligned.m8n8.x4.shared.b16 {%0,%1,%2,%3}, [%4];"
        : "=r"(a[0]), "=r"(a[1]), "=r"(a[2]), "=r"(a[3]) : "r"(addr));
}
__device__ __forceinline__ void mma16(float* d, const uint32_t* a, uint2 b) {
    asm volatile("mma.sync.aligned.m16n8k16.row.col.f32.bf16.bf16.f32 "
        "{%0,%1,%2,%3},{%4,%5,%6,%7},{%8,%9},{%0,%1,%2,%3};"
        : "+f"(d[0]), "+f"(d[1]), "+f"(d[2]), "+f"(d[3])
        : "r"(a[0]), "r"(a[1]), "r"(a[2]), "r"(a[3]), "r"(b.x), "r"(b.y));
}
__device__ __forceinline__ float tanha(float x) {
    float y; asm("tanh.approx.f32 %0,%1;" : "=f"(y) : "f"(x)); return y;
}
__device__ __forceinline__ float siga(float x) {
    return fmaf(0.5f, tanha(0.5f * x), 0.5f);
}

// ============================================================================
// Fused PRNN kernel. 64 samples/CTA, 256 threads (8 warps).
// Warp w owns cols [16w,16w+16) of all 64 rows (3 gates + hid).
// Per iter: ONE A-load loop feeding gate MMAs (step t) AND hid MMA (step t-1);
// epilogue: h_t -> sA (bf16) and register-path logits partials (no hid smem).
// ============================================================================
__global__ __launch_bounds__(THREADS, 1) void prnn_kernel(
    const float* __restrict__ x, const float* __restrict__ w_ih,
    const float* __restrict__ w_hh, const float* __restrict__ b_ih,
    const float* __restrict__ b_hh, const float* __restrict__ w1,
    const float* __restrict__ b1, const float* __restrict__ w2,
    const float* __restrict__ b2, float* __restrict__ out)
{
    extern __shared__ char sm[];
    uint2*  sBW  = (uint2*)(sm + S_BW);
    uint2*  sBW1 = (uint2*)(sm + S_BW1);
    float4* sXI  = (float4*)(sm + S_XI);
    unsigned char* sP = (unsigned char*)(sm + S_P);
    float*  sPart = (float*)(sm + S_PART);

    const int tid = threadIdx.x;
    const int wid = tid >> 5, lane = tid & 31;
    const int rg = lane >> 2, c4 = lane & 3;
    const int j0 = wid * 16;
    const int bBase = blockIdx.x * TPC;
    const uint32_t saB = s2u(sm + S_A);

    // ---- stage W_hh / w1 B-frags (bf16) ----
    for (int i = tid; i < 8 * 48 * 32; i += THREADS) {
        int ln = i & 31, nf = (i >> 5) % 48, kc = (i >> 5) / 48;
        const float* wr = w_hh + (nf * 8 + (ln >> 2)) * NH + kc * 16 + (ln & 3) * 2;
        sBW[i] = make_uint2(bf2(wr[0], wr[1]), bf2(wr[8], wr[9]));
    }
    for (int i = tid; i < 8 * 16 * 32; i += THREADS) {
        int ln = i & 31, nf = (i >> 5) % 16, kc = (i >> 5) / 16;
        const float* wr = w1 + (nf * 8 + (ln >> 2)) * NH + kc * 16 + (ln & 3) * 2;
        sBW1[i] = make_uint2(bf2(wr[0], wr[1]), bf2(wr[8], wr[9]));
    }
    // ---- xi table: [v][j] = {xi_r, xi_z, xi_n, b_hh_n} ----
    for (int i = tid; i < 4 * NH; i += THREADS) {
        int v = i >> 7, j = i & 127;
        float xr = b_ih[j] + b_hh[j];
        float xz = b_ih[NH + j] + b_hh[NH + j];
        float xn = b_ih[2 * NH + j];
        if (v & 1) { xr += w_ih[j * 2]; xz += w_ih[(NH + j) * 2]; xn += w_ih[(2 * NH + j) * 2]; }
        if (v & 2) { xr += w_ih[j * 2 + 1]; xz += w_ih[(NH + j) * 2 + 1]; xn += w_ih[(2 * NH + j) * 2 + 1]; }
        sXI[i] = make_float4(xr, xz, xn, b_hh[2 * NH + j]);
    }
    // ---- patch indices ----
    for (int i = tid; i < T_STEPS * TPC; i += THREADS) {
        int t = i >> 6, s = i & 63;
        const float* xb = x + (size_t)(bBase + s) * SEQ_L + 2 * t;
        sP[i] = (unsigned char)((xb[0] != 0.0f ? 1 : 0) | (xb[1] != 0.0f ? 2 : 0));
    }
    // ---- zero A (h0 = 0) ----
    for (int i = tid; i < 4352; i += THREADS) ((uint32_t*)(sm + S_A))[i] = 0u;

    // ---- per-thread constants: b1 & w2 for this thread's 4 cols; b2 for its o ----
    // col(ci): ci = f*2 + lo -> j0 + f*8 + 2*c4 + lo
    float b1c[4], w2c[4][4];
    #pragma unroll
    for (int ci = 0; ci < 4; ci++) {
        int col = j0 + (ci >> 1) * 8 + 2 * c4 + (ci & 1);
        b1c[ci] = b1[col];
        #pragma unroll
        for (int o = 0; o < 4; o++) w2c[ci][o] = w2[o * NH + col];
    }
    const float b2r = b2[tid & 3];

    float hp[4][2][4];
    #pragma unroll
    for (int m = 0; m < 4; m++)
        #pragma unroll
        for (int f = 0; f < 2; f++)
            #pragma unroll
            for (int e = 0; e < 4; e++) hp[m][f][e] = 0.0f;
    float acc = 0.0f;

    const uint32_t lmBase = saB + (uint32_t)(lane & 15) * 272 + (uint32_t)(lane >> 4) * 16;

    __syncthreads();

    for (int t = 0; t <= T_STEPS; t++) {
        // ---------- merged MMA loop: gates (step t) + hid (step t-1), one A load ----------
        float aR[4][2][4], aZ[4][2][4], aN[4][2][4], aH[4][2][4];
        #pragma unroll
        for (int m = 0; m < 4; m++)
            #pragma unroll
            for (int f = 0; f < 2; f++)
                #pragma unroll
                for (int e = 0; e < 4; e++) {
                    aR[m][f][e] = 0.f; aZ[m][f][e] = 0.f; aN[m][f][e] = 0.f; aH[m][f][e] = 0.f;
                }
        #pragma unroll
        for (int kc = 0; kc < 8; kc++) {
            uint32_t A[4][4];
            #pragma unroll
            for (int m = 0; m < 4; m++) ldm4(A[m], lmBase + m * 16 * 272 + kc * 32);
            #pragma unroll
            for (int f = 0; f < 2; f++) {
                if (t < T_STEPS) {
                    uint2 Br = sBW[(kc * 48 + 0 * 16 + wid * 2 + f) * 32 + lane];
                    uint2 Bz = sBW[(kc * 48 + 1 * 16 + wid * 2 + f) * 32 + lane];
                    uint2 Bn = sBW[(kc * 48 + 2 * 16 + wid * 2 + f) * 32 + lane];
                    #pragma unroll
                    for (int m = 0; m < 4; m++) {
                        mma16(aR[m][f], A[m], Br);
                        mma16(aZ[m][f], A[m], Bz);
                        mma16(aN[m][f], A[m], Bn);
                    }
                }
                if (t >= 1) {
                    uint2 Bh = sBW1[(kc * 16 + wid * 2 + f) * 32 + lane];
                    #pragma unroll
                    for (int m = 0; m < 4; m++) mma16(aH[m][f], A[m], Bh);
                }
            }
        }

        __syncthreads();   // all sA reads (ldmatrix) done

        // ---------- gate epilogue: h_t -> sA (bf16) ----------
        if (t < T_STEPS) {
            #pragma unroll
            for (int m = 0; m < 4; m++)
                #pragma unroll
                for (int rr = 0; rr < 2; rr++) {
                    int row = m * 16 + rg + rr * 8;
                    int v = (t > 0) ? sP[(t - 1) * TPC + row] : 0;
                    #pragma unroll
                    for (int f = 0; f < 2; f++) {
                        int col0 = j0 + f * 8 + 2 * c4;
                        int e0 = rr * 2, e1 = rr * 2 + 1;
                        float4 xa = sXI[v * NH + col0];
                        float4 xb = sXI[v * NH + col0 + 1];
                        float r0 = siga(aR[m][f][e0] + xa.x);
                        float r1 = siga(aR[m][f][e1] + xb.x);
                        float z0 = siga(aZ[m][f][e0] + xa.y);
                        float z1 = siga(aZ[m][f][e1] + xb.y);
                        float n0 = tanha(xa.z + r0 * (aN[m][f][e0] + xa.w));
                        float n1 = tanha(xb.z + r1 * (aN[m][f][e1] + xb.w));
                        float h0 = n0 + z0 * (hp[m][f][e0] - n0);
                        float h1 = n1 + z1 * (hp[m][f][e1] - n1);
                        hp[m][f][e0] = h0; hp[m][f][e1] = h1;
                        *(uint32_t*)(sm + S_A + row * 272 + col0 * 2) = bf2(h0, h1);
                    }
                }
        }

        // ---------- hid partials for step t-1 (registers -> shfl -> sPart) ----------
        if (t >= 1) {
            float p[8][4];
            #pragma unroll
            for (int q = 0; q < 8; q++)
                #pragma unroll
                for (int o = 0; o < 4; o++) p[q][o] = 0.0f;
            #pragma unroll
            for (int m = 0; m < 4; m++)
                #pragma unroll
                for (int f = 0; f < 2; f++)
                    #pragma unroll
                    for (int e = 0; e < 4; e++) {
                        int ci = f * 2 + (e & 1);
                        int q = m * 2 + (e >> 1);          // row instance (rr in bit 1 of e)
                        float hid = fmaxf(aH[m][f][e] + b1c[ci], 0.0f);
                        #pragma unroll
                        for (int o = 0; o < 4; o++) p[q][o] = fmaf(hid, w2c[ci][o], p[q][o]);
                    }
            // reduce over the 4 col-lanes (c4)
            #pragma unroll
            for (int q = 0; q < 8; q++)
                #pragma unroll
                for (int o = 0; o < 4; o++) {
                    float v = p[q][o];
                    v += __shfl_xor_sync(0xffffffffu, v, 1);
                    v += __shfl_xor_sync(0xffffffffu, v, 2);
                    p[q][o] = v;
                }
            if (c4 == 0) {
                float4* dst = (float4*)(sPart + (size_t)(t & 1) * 8 * 64 * 4 + wid * 64 * 4);
                #pragma unroll
                for (int q = 0; q < 8; q++) {
                    int row = (q >> 1) * 16 + rg + (q & 1) * 8;
                    dst[row] = make_float4(p[q][0], p[q][1], p[q][2], p[q][3]);
                }
            }
        }

        __syncthreads();   // sA + sPart ready

        // ---------- logits + logsumexp for step t-1 ----------
        if (t >= 1) {
            int row = tid >> 2;
            const float* pb = sPart + (size_t)(t & 1) * 8 * 64 * 4 + row * 4 + (tid & 3);
            float l = b2r;
            #pragma unroll
            for (int w = 0; w < 8; w++) l += pb[w * 64 * 4];
            float m1 = fmaxf(l, __shfl_xor_sync(0xffffffffu, l, 1));
            float mx = fmaxf(m1, __shfl_xor_sync(0xffffffffu, m1, 2));
            float e = __expf(l - mx);
            float s = e + __shfl_xor_sync(0xffffffffu, e, 1);
            s += __shfl_xor_sync(0xffffffffu, s, 2);
            float lse = mx + __logf(s);
            int idx = sP[(t - 1) * TPC + row];
            float lpick = __shfl_sync(0xffffffffu, l, (lane & ~3) | idx);
            if ((tid & 3) == 0) acc += lpick - lse;
        }
    }

    if ((tid & 3) == 0) out[bBase + (tid >> 2)] = acc;
}

extern "C" void kernel_launch(void* const* d_in, const int* in_sizes, int n_in,
                              void* d_out, int out_size) {
    const float* x    = (const float*)d_in[0];
    const float* w_ih = (const float*)d_in[1];
    const float* w_hh = (const float*)d_in[2];
    const float* b_ih = (const float*)d_in[3];
    const float* b_hh = (const float*)d_in[4];
    const float* w1   = (const float*)d_in[5];
    const float* b1   = (const float*)d_in[6];
    const float* w2   = (const float*)d_in[7];
    const float* b2   = (const float*)d_in[8];
    float* out = (float*)d_out;

    cudaFuncSetAttribute(prnn_kernel, cudaFuncAttributeMaxDynamicSharedMemorySize, SMEM_TOTAL);
    prnn_kernel<<<NCTA, THREADS, SMEM_TOTAL>>>(
        x, w_ih, w_hh, b_ih, b_hh, w1, b1, w2, b2, out);
}

// round 9
// speedup vs baseline: 7.6460x; 1.0480x over previous
#include <cuda_runtime.h>
#include <cstdint>

#define BATCH   16384
#define SEQ_L   64
#define T_STEPS 32
#define NH      128
#define TPC     64
#define NCTA    (BATCH / TPC)   // 256
#define THREADS 256

// ---------------- smem layout (bytes) ----------------
#define S_BW   0                 // W_hh bf16 B-frags: 8kc*48nf*32lane uint2 = 98304
#define S_BW1  98304             // w1  bf16 B-frags: 8kc*16nf*32lane uint2 = 32768
#define S_A0   131072            // h tile (parity 0) bf16 [64][136]         = 17408
#define S_A1   148480            // h tile (parity 1) bf16 [64][136]         = 17408
#define S_P    165888            // uint8 patch idx [32][64]                 = 2048
#define S_PART 167936            // f32 partial logits [2 par][8 w][64][4]   = 16384
#define SMEM_TOTAL 184320
#define A_BUFSZ 17408

// ---------------- helpers ----------------
__device__ __forceinline__ uint32_t s2u(const void* p) {
    uint32_t a;
    asm("{ .reg .u64 t; cvta.to.shared.u64 t, %1; cvt.u32.u64 %0, t; }" : "=r"(a) : "l"(p));
    return a;
}
__device__ __forceinline__ uint32_t bf2(float lo, float hi) {
    uint32_t r; asm("cvt.rn.bf16x2.f32 %0, %1, %2;" : "=r"(r) : "f"(hi), "f"(lo)); return r;
}
__device__ __forceinline__ void ldm4(uint32_t* a, uint32_t addr) {
    asm volatile("ldmatrix.sync.aligned.m8n8.x4.shared.b16 {%0,%1,%2,%3}, [%4];"
        : "=r"(a[0]), "=r"(a[1]), "=r"(a[2]), "=r"(a[3]) : "r"(addr));
}
__device__ __forceinline__ void mma16(float* d, const uint32_t* a, uint2 b) {
    asm volatile("mma.sync.aligned.m16n8k16.row.col.f32.bf16.bf16.f32 "
        "{%0,%1,%2,%3},{%4,%5,%6,%7},{%8,%9},{%0,%1,%2,%3};"
        : "+f"(d[0]), "+f"(d[1]), "+f"(d[2]), "+f"(d[3])
        : "r"(a[0]), "r"(a[1]), "r"(a[2]), "r"(a[3]), "r"(b.x), "r"(b.y));
}
__device__ __forceinline__ float tanha(float x) {
    float y; asm("tanh.approx.f32 %0,%1;" : "=f"(y) : "f"(x)); return y;
}
__device__ __forceinline__ float siga(float x) {
    return fmaf(0.5f, tanha(0.5f * x), 0.5f);
}

// ============================================================================
// Fused PRNN. 64 samples/CTA, 256 threads (8 warps), warp owns 16 cols.
// Double-buffered A tile -> ONE barrier per iteration. xi input-projections
// live in 40 per-thread registers (affine in the 2 input bits) - no table.
// Iter t: MMA(gates t + hid t-1) from sA[t&1]; lse for step t-2; epilogue
// writes h_t -> sA[(t+1)&1] and head partials (t-1) -> sPart[t&1].
// ============================================================================
__global__ __launch_bounds__(THREADS, 1) void prnn_kernel(
    const float* __restrict__ x, const float* __restrict__ w_ih,
    const float* __restrict__ w_hh, const float* __restrict__ b_ih,
    const float* __restrict__ b_hh, const float* __restrict__ w1,
    const float* __restrict__ b1, const float* __restrict__ w2,
    const float* __restrict__ b2, float* __restrict__ out)
{
    extern __shared__ char sm[];
    uint2*  sBW  = (uint2*)(sm + S_BW);
    uint2*  sBW1 = (uint2*)(sm + S_BW1);
    unsigned char* sP = (unsigned char*)(sm + S_P);
    float*  sPart = (float*)(sm + S_PART);

    const int tid = threadIdx.x;
    const int wid = tid >> 5, lane = tid & 31;
    const int rg = lane >> 2, c4 = lane & 3;
    const int j0 = wid * 16;
    const int bBase = blockIdx.x * TPC;
    const uint32_t saB = s2u(sm + S_A0);

    // ---- stage W_hh / w1 B-frags (bf16) ----
    for (int i = tid; i < 8 * 48 * 32; i += THREADS) {
        int ln = i & 31, nf = (i >> 5) % 48, kc = (i >> 5) / 48;
        const float* wr = w_hh + (nf * 8 + (ln >> 2)) * NH + kc * 16 + (ln & 3) * 2;
        sBW[i] = make_uint2(bf2(wr[0], wr[1]), bf2(wr[8], wr[9]));
    }
    for (int i = tid; i < 8 * 16 * 32; i += THREADS) {
        int ln = i & 31, nf = (i >> 5) % 16, kc = (i >> 5) / 16;
        const float* wr = w1 + (nf * 8 + (ln >> 2)) * NH + kc * 16 + (ln & 3) * 2;
        sBW1[i] = make_uint2(bf2(wr[0], wr[1]), bf2(wr[8], wr[9]));
    }
    // ---- patch indices ----
    for (int i = tid; i < T_STEPS * TPC; i += THREADS) {
        int t = i >> 6, s = i & 63;
        const float* xb = x + (size_t)(bBase + s) * SEQ_L + 2 * t;
        sP[i] = (unsigned char)((xb[0] != 0.0f ? 1 : 0) | (xb[1] != 0.0f ? 2 : 0));
    }
    // ---- zero both A buffers (h_{-1} = 0; buf1 fully rewritten in iter 0) ----
    for (int i = tid; i < 2 * A_BUFSZ / 4; i += THREADS) ((uint32_t*)(sm + S_A0))[i] = 0u;

    // ---- per-thread xi registers: cols ci=0..3 -> j0 + (ci>>1)*8 + 2*c4 + (ci&1) ----
    float baseR[4], wR0[4], wR1[4], baseZ[4], wZ0[4], wZ1[4];
    float baseN[4], wN0[4], wN1[4], bhn[4], b1c[4], w2c[4][4];
    #pragma unroll
    for (int ci = 0; ci < 4; ci++) {
        int col = j0 + (ci >> 1) * 8 + 2 * c4 + (ci & 1);
        baseR[ci] = b_ih[col] + b_hh[col];
        wR0[ci] = w_ih[col * 2]; wR1[ci] = w_ih[col * 2 + 1];
        baseZ[ci] = b_ih[NH + col] + b_hh[NH + col];
        wZ0[ci] = w_ih[(NH + col) * 2]; wZ1[ci] = w_ih[(NH + col) * 2 + 1];
        baseN[ci] = b_ih[2 * NH + col];
        wN0[ci] = w_ih[(2 * NH + col) * 2]; wN1[ci] = w_ih[(2 * NH + col) * 2 + 1];
        bhn[ci] = b_hh[2 * NH + col];
        b1c[ci] = b1[col];
        #pragma unroll
        for (int o = 0; o < 4; o++) w2c[ci][o] = w2[o * NH + col];
    }
    const float b2r = b2[tid & 3];

    float hp[4][2][4];
    #pragma unroll
    for (int m = 0; m < 4; m++)
        #pragma unroll
        for (int f = 0; f < 2; f++)
            #pragma unroll
            for (int e = 0; e < 4; e++) hp[m][f][e] = 0.0f;
    float acc = 0.0f;

    const uint32_t lmBase = saB + (uint32_t)(lane & 15) * 272 + (uint32_t)(lane >> 4) * 16;

    for (int t = 0; t <= T_STEPS + 1; t++) {
        __syncthreads();   // sA[t&1] and sPart[(t-1)&1] complete

        const uint32_t abuf = (uint32_t)(t & 1) * A_BUFSZ;

        // ---------- merged MMA: gates (step t) + hid (step t-1) ----------
        float aR[4][2][4], aZ[4][2][4], aN[4][2][4], aH[4][2][4];
        #pragma unroll
        for (int m = 0; m < 4; m++)
            #pragma unroll
            for (int f = 0; f < 2; f++)
                #pragma unroll
                for (int e = 0; e < 4; e++) {
                    aR[m][f][e] = 0.f; aZ[m][f][e] = 0.f; aN[m][f][e] = 0.f; aH[m][f][e] = 0.f;
                }
        if (t <= T_STEPS) {
            #pragma unroll
            for (int kc = 0; kc < 8; kc++) {
                uint32_t A[4][4];
                #pragma unroll
                for (int m = 0; m < 4; m++) ldm4(A[m], lmBase + abuf + m * 16 * 272 + kc * 32);
                #pragma unroll
                for (int f = 0; f < 2; f++) {
                    if (t < T_STEPS) {
                        uint2 Br = sBW[(kc * 48 + 0 * 16 + wid * 2 + f) * 32 + lane];
                        uint2 Bz = sBW[(kc * 48 + 1 * 16 + wid * 2 + f) * 32 + lane];
                        uint2 Bn = sBW[(kc * 48 + 2 * 16 + wid * 2 + f) * 32 + lane];
                        #pragma unroll
                        for (int m = 0; m < 4; m++) {
                            mma16(aR[m][f], A[m], Br);
                            mma16(aZ[m][f], A[m], Bz);
                            mma16(aN[m][f], A[m], Bn);
                        }
                    }
                    if (t >= 1) {
                        uint2 Bh = sBW1[(kc * 16 + wid * 2 + f) * 32 + lane];
                        #pragma unroll
                        for (int m = 0; m < 4; m++) mma16(aH[m][f], A[m], Bh);
                    }
                }
            }
        }

        // ---------- logits + logsumexp for step t-2 (hides under MMA latency) ----------
        if (t >= 2) {
            int row = tid >> 2;
            const float* pb = sPart + (size_t)((t - 1) & 1) * 2048 + row * 4 + (tid & 3);
            float l = b2r;
            #pragma unroll
            for (int w = 0; w < 8; w++) l += pb[w * 256];
            float m1 = fmaxf(l, __shfl_xor_sync(0xffffffffu, l, 1));
            float mx = fmaxf(m1, __shfl_xor_sync(0xffffffffu, m1, 2));
            float e = __expf(l - mx);
            float s = e + __shfl_xor_sync(0xffffffffu, e, 1);
            s += __shfl_xor_sync(0xffffffffu, s, 2);
            float lse = mx + __logf(s);
            int idx = sP[(t - 2) * TPC + row];
            float lpick = __shfl_sync(0xffffffffu, l, (lane & ~3) | idx);
            if ((tid & 3) == 0) acc += lpick - lse;
        }

        // ---------- gate epilogue: h_t -> sA[(t+1)&1] ----------
        if (t < T_STEPS) {
            const uint32_t wbuf = (uint32_t)((t + 1) & 1) * A_BUFSZ;
            #pragma unroll
            for (int m = 0; m < 4; m++)
                #pragma unroll
                for (int rr = 0; rr < 2; rr++) {
                    int row = m * 16 + rg + rr * 8;
                    int v = (t > 0) ? sP[(t - 1) * TPC + row] : 0;
                    float d0 = (float)(v & 1), d1 = (float)(v >> 1);
                    #pragma unroll
                    for (int f = 0; f < 2; f++) {
                        float hh[2];
                        #pragma unroll
                        for (int lo = 0; lo < 2; lo++) {
                            int ci = f * 2 + lo, e = rr * 2 + lo;
                            float xr = fmaf(d1, wR1[ci], fmaf(d0, wR0[ci], baseR[ci]));
                            float xz = fmaf(d1, wZ1[ci], fmaf(d0, wZ0[ci], baseZ[ci]));
                            float xn = fmaf(d1, wN1[ci], fmaf(d0, wN0[ci], baseN[ci]));
                            float r = siga(aR[m][f][e] + xr);
                            float z = siga(aZ[m][f][e] + xz);
                            float n = tanha(xn + r * (aN[m][f][e] + bhn[ci]));
                            float h = n + z * (hp[m][f][e] - n);
                            hp[m][f][e] = h;
                            hh[lo] = h;
                        }
                        int col0 = j0 + f * 8 + 2 * c4;
                        *(uint32_t*)(sm + S_A0 + wbuf + row * 272 + col0 * 2) = bf2(hh[0], hh[1]);
                    }
                }
        }

        // ---------- head partials for step t-1 -> sPart[t&1] ----------
        if (t >= 1 && t <= T_STEPS) {
            float p[8][4];
            #pragma unroll
            for (int q = 0; q < 8; q++)
                #pragma unroll
                for (int o = 0; o < 4; o++) p[q][o] = 0.0f;
            #pragma unroll
            for (int m = 0; m < 4; m++)
                #pragma unroll
                for (int f = 0; f < 2; f++)
                    #pragma unroll
                    for (int e = 0; e < 4; e++) {
                        int ci = f * 2 + (e & 1);
                        int q = m * 2 + (e >> 1);
                        float hid = fmaxf(aH[m][f][e] + b1c[ci], 0.0f);
                        #pragma unroll
                        for (int o = 0; o < 4; o++) p[q][o] = fmaf(hid, w2c[ci][o], p[q][o]);
                    }
            #pragma unroll
            for (int q = 0; q < 8; q++)
                #pragma unroll
                for (int o = 0; o < 4; o++) {
                    float v = p[q][o];
                    v += __shfl_xor_sync(0xffffffffu, v, 1);
                    v += __shfl_xor_sync(0xffffffffu, v, 2);
                    p[q][o] = v;
                }
            if (c4 == 0) {
                float4* dst = (float4*)(sPart + (size_t)(t & 1) * 2048 + wid * 256);
                #pragma unroll
                for (int q = 0; q < 8; q++) {
                    int row = (q >> 1) * 16 + rg + (q & 1) * 8;
                    dst[row] = make_float4(p[q][0], p[q][1], p[q][2], p[q][3]);
                }
            }
        }
    }

    if ((tid & 3) == 0) out[bBase + (tid >> 2)] = acc;
}

extern "C" void kernel_launch(void* const* d_in, const int* in_sizes, int n_in,
                              void* d_out, int out_size) {
    const float* x    = (const float*)d_in[0];
    const float* w_ih = (const float*)d_in[1];
    const float* w_hh = (const float*)d_in[2];
    const float* b_ih = (const float*)d_in[3];
    const float* b_hh = (const float*)d_in[4];
    const float* w1   = (const float*)d_in[5];
    const float* b1   = (const float*)d_in[6];
    const float* w2   = (const float*)d_in[7];
    const float* b2   = (const float*)d_in[8];
    float* out = (float*)d_out;

    cudaFuncSetAttribute(prnn_kernel, cudaFuncAttributeMaxDynamicSharedMemorySize, SMEM_TOTAL);
    prnn_kernel<<<NCTA, THREADS, SMEM_TOTAL>>>(
        x, w_ih, w_hh, b_ih, b_hh, w1, b1, w2, b2, out);
}